// round 1
// baseline (speedup 1.0000x reference)
#include <cuda_runtime.h>
#include <cstdint>
#include <cstddef>

#define B_ 16384
#define D_ 256
#define H_ 1024

// ---------------- scratch (device globals: no allocation allowed) ----------------
__device__ float g_noise[B_ * D_];
__device__ float g_h1[B_ * H_];
__device__ float g_dh1[B_ * H_];
__device__ float g_h2[B_ * H_];
__device__ float g_dh2[B_ * H_];
__device__ float g_v[4][B_ * D_];
__device__ float g_trp[4][8][B_];
__device__ float g_xt[B_ * D_];
__device__ float g_xe[B_ * D_];
__device__ float g_ljt[B_];

// ---------------- helpers ----------------
__device__ __forceinline__ float f2tf(float f) {
    uint32_t u;
    asm("cvt.rna.tf32.f32 %0, %1;" : "=r"(u) : "f"(f));
    return __uint_as_float(u);
}

__device__ __forceinline__ void mma8(float* d, const float* a, const float* b) {
    asm volatile(
        "mma.sync.aligned.m16n8k8.row.col.f32.tf32.tf32.f32 "
        "{%0,%1,%2,%3}, {%4,%5,%6,%7}, {%8,%9}, {%0,%1,%2,%3};"
        : "+f"(d[0]), "+f"(d[1]), "+f"(d[2]), "+f"(d[3])
        : "r"(__float_as_uint(a[0])), "r"(__float_as_uint(a[1])),
          "r"(__float_as_uint(a[2])), "r"(__float_as_uint(a[3])),
          "r"(__float_as_uint(b[0])), "r"(__float_as_uint(b[1])));
}

// ---------------- dual-stream tf32 GEMM mainloop ----------------
// Block: 128 threads (4 warps in 2x2), tile 64(M) x 64(N) per stream, BK=16.
// Computes accv = Av(64xK) * W(KxN tile), acct = At(64xK) * W(KxN tile).
__device__ __forceinline__ void dual_gemm_core(
    const float* __restrict__ Av, const float* __restrict__ At,
    const float* __restrict__ W, int K, int N,
    float accv[2][4][4], float acct[2][4][4])
{
    __shared__ float Asv[64][20];   // pad 20 -> conflict-free frag loads
    __shared__ float Ast[64][20];
    __shared__ float Bs[16][72];    // pad 72 -> conflict-free frag loads

    const int m0 = blockIdx.y * 64;
    const int n0 = blockIdx.x * 64;
    const int tid = threadIdx.x;
    const int lane = tid & 31;
    const int warp = tid >> 5;
    const int g = lane >> 2, tg = lane & 3;
    const int wm = (warp >> 1) * 32, wn = (warp & 1) * 32;

#pragma unroll
    for (int mi = 0; mi < 2; mi++)
#pragma unroll
        for (int ni = 0; ni < 4; ni++)
#pragma unroll
            for (int e = 0; e < 4; e++) { accv[mi][ni][e] = 0.f; acct[mi][ni][e] = 0.f; }

    for (int k0 = 0; k0 < K; k0 += 16) {
#pragma unroll
        for (int i = 0; i < 2; i++) {
            int idx = tid + i * 128;
            int ar = idx >> 2, ac = (idx & 3) * 4;          // A: 64 rows x 4 float4
            float4 a4 = *(const float4*)(Av + (size_t)(m0 + ar) * K + k0 + ac);
            Asv[ar][ac + 0] = f2tf(a4.x); Asv[ar][ac + 1] = f2tf(a4.y);
            Asv[ar][ac + 2] = f2tf(a4.z); Asv[ar][ac + 3] = f2tf(a4.w);
            float4 t4 = *(const float4*)(At + (size_t)(m0 + ar) * K + k0 + ac);
            Ast[ar][ac + 0] = f2tf(t4.x); Ast[ar][ac + 1] = f2tf(t4.y);
            Ast[ar][ac + 2] = f2tf(t4.z); Ast[ar][ac + 3] = f2tf(t4.w);
            int br = idx >> 4, bc = (idx & 15) * 4;         // B: 16 rows x 16 float4
            float4 w4 = *(const float4*)(W + (size_t)(k0 + br) * N + n0 + bc);
            Bs[br][bc + 0] = f2tf(w4.x); Bs[br][bc + 1] = f2tf(w4.y);
            Bs[br][bc + 2] = f2tf(w4.z); Bs[br][bc + 3] = f2tf(w4.w);
        }
        __syncthreads();
#pragma unroll
        for (int kk = 0; kk < 16; kk += 8) {
            float av[2][4], at[2][4], bf[4][2];
#pragma unroll
            for (int mi = 0; mi < 2; mi++) {
                int r = wm + mi * 16 + g;
                av[mi][0] = Asv[r][kk + tg];       av[mi][1] = Asv[r + 8][kk + tg];
                av[mi][2] = Asv[r][kk + tg + 4];   av[mi][3] = Asv[r + 8][kk + tg + 4];
                at[mi][0] = Ast[r][kk + tg];       at[mi][1] = Ast[r + 8][kk + tg];
                at[mi][2] = Ast[r][kk + tg + 4];   at[mi][3] = Ast[r + 8][kk + tg + 4];
            }
#pragma unroll
            for (int ni = 0; ni < 4; ni++) {
                int cn = wn + ni * 8 + g;
                bf[ni][0] = Bs[kk + tg][cn];
                bf[ni][1] = Bs[kk + tg + 4][cn];
            }
#pragma unroll
            for (int mi = 0; mi < 2; mi++)
#pragma unroll
                for (int ni = 0; ni < 4; ni++) {
                    mma8(accv[mi][ni], av[mi], bf[ni]);
                    mma8(acct[mi][ni], at[mi], bf[ni]);
                }
        }
        __syncthreads();
    }
}

// ---------------- hidden layers: fused tanh / tanh' epilogue ----------------
__global__ void __launch_bounds__(128)
gemm_tanh_kernel(const float* __restrict__ Av, const float* __restrict__ At,
                 const float* __restrict__ W, const float* __restrict__ bias,
                 const float* __restrict__ wt, float tval,
                 float* __restrict__ Ho, float* __restrict__ Do, int K, int N)
{
    float accv[2][4][4], acct[2][4][4];
    dual_gemm_core(Av, At, W, K, N, accv, acct);

    const int m0 = blockIdx.y * 64, n0 = blockIdx.x * 64;
    const int lane = threadIdx.x & 31, warp = threadIdx.x >> 5;
    const int g = lane >> 2, tg = lane & 3;
    const int wm = (warp >> 1) * 32, wn = (warp & 1) * 32;

#pragma unroll
    for (int mi = 0; mi < 2; mi++)
#pragma unroll
        for (int ni = 0; ni < 4; ni++)
#pragma unroll
            for (int e = 0; e < 4; e++) {
                int row = m0 + wm + mi * 16 + g + ((e & 2) ? 8 : 0);
                int col = n0 + wn + ni * 8 + 2 * tg + (e & 1);
                float bz = bias[col];
                if (wt) bz += tval * wt[col];
                float h = tanhf(accv[mi][ni][e] + bz);
                size_t o = (size_t)row * N + col;
                Ho[o] = h;
                Do[o] = (1.f - h * h) * acct[mi][ni][e];
            }
}

// ---------------- output layer: fused v / jv / trace-partials / eval-point ----------------
__global__ void __launch_bounds__(128)
gemm_out_kernel(const float* __restrict__ Av, const float* __restrict__ At,
                const float* __restrict__ W, const float* __restrict__ bias,
                int K, int N,
                float* __restrict__ Vo, float* __restrict__ Trp,
                const float* __restrict__ Noise, const float* __restrict__ Xt,
                float* __restrict__ Xe, float cEval)
{
    float accv[2][4][4], acct[2][4][4];
    dual_gemm_core(Av, At, W, K, N, accv, acct);

    const int m0 = blockIdx.y * 64, n0 = blockIdx.x * 64;
    const int lane = threadIdx.x & 31, warp = threadIdx.x >> 5;
    const int g = lane >> 2, tg = lane & 3;
    const int wm = (warp >> 1) * 32, wn = (warp & 1) * 32;

    float rs[2][2] = {{0.f, 0.f}, {0.f, 0.f}};
#pragma unroll
    for (int mi = 0; mi < 2; mi++)
#pragma unroll
        for (int ni = 0; ni < 4; ni++)
#pragma unroll
            for (int e = 0; e < 4; e++) {
                int row = m0 + wm + mi * 16 + g + ((e & 2) ? 8 : 0);
                int col = n0 + wn + ni * 8 + 2 * tg + (e & 1);
                size_t o = (size_t)row * N + col;
                float v = accv[mi][ni][e] + bias[col];
                Vo[o] = v;
                if (cEval != 0.f) Xe[o] = Xt[o] + cEval * v;
                rs[mi][(e & 2) >> 1] += Noise[o] * acct[mi][ni][e];
            }
    // reduce over the 4 lanes (tg) sharing each row; deterministic partial per (n-tile, warp-n-half)
#pragma unroll
    for (int mi = 0; mi < 2; mi++)
#pragma unroll
        for (int hf = 0; hf < 2; hf++) {
            float s = rs[mi][hf];
            s += __shfl_xor_sync(0xffffffffu, s, 1);
            s += __shfl_xor_sync(0xffffffffu, s, 2);
            if (tg == 0) {
                int row = m0 + wm + mi * 16 + g + hf * 8;
                Trp[(size_t)(blockIdx.x * 2 + (warp & 1)) * B_ + row] = s;
            }
        }
}

// ---------------- noise = sin(1000*(x@proj))*sqrt(2), plain fp32 ----------------
__global__ void __launch_bounds__(256)
noise_kernel(const float* __restrict__ X, const float* __restrict__ P)
{
    __shared__ float As[64][17];
    __shared__ float Bs[16][68];
    int bm = blockIdx.y * 64, bn = blockIdx.x * 64;
    int tx = threadIdx.x, ty = threadIdx.y;
    int tid = ty * 16 + tx;
    float acc[4][4];
#pragma unroll
    for (int i = 0; i < 4; i++)
#pragma unroll
        for (int j = 0; j < 4; j++) acc[i][j] = 0.f;

    for (int k0 = 0; k0 < D_; k0 += 16) {
        int ar = tid >> 2, ac = (tid & 3) * 4;
        float4 a4 = *(const float4*)(X + (size_t)(bm + ar) * D_ + k0 + ac);
        As[ar][ac + 0] = a4.x; As[ar][ac + 1] = a4.y; As[ar][ac + 2] = a4.z; As[ar][ac + 3] = a4.w;
        int br = tid >> 4, bc = (tid & 15) * 4;
        float4 b4 = *(const float4*)(P + (size_t)(k0 + br) * D_ + bn + bc);
        Bs[br][bc + 0] = b4.x; Bs[br][bc + 1] = b4.y; Bs[br][bc + 2] = b4.z; Bs[br][bc + 3] = b4.w;
        __syncthreads();
#pragma unroll
        for (int k = 0; k < 16; k++) {
            float a[4], b[4];
#pragma unroll
            for (int i = 0; i < 4; i++) a[i] = As[ty * 4 + i][k];
#pragma unroll
            for (int j = 0; j < 4; j++) b[j] = Bs[k][tx * 4 + j];
#pragma unroll
            for (int i = 0; i < 4; i++)
#pragma unroll
                for (int j = 0; j < 4; j++) acc[i][j] = fmaf(a[i], b[j], acc[i][j]);
        }
        __syncthreads();
    }
#pragma unroll
    for (int i = 0; i < 4; i++)
#pragma unroll
        for (int j = 0; j < 4; j++)
            g_noise[(size_t)(bm + ty * 4 + i) * D_ + bn + tx * 4 + j] =
                sinf(1000.f * acc[i][j]) * 1.41421356f;
}

// ---------------- small kernels ----------------
__global__ void init_kernel(const float* __restrict__ X)
{
    int i = blockIdx.x * blockDim.x + threadIdx.x;
    g_xt[i] = X[i];
    if (i < B_) g_ljt[i] = 0.f;
}

__global__ void combine_kernel(float c)   // c = dt/6
{
    int i = blockIdx.x * blockDim.x + threadIdx.x;
    g_xt[i] += c * (g_v[0][i] + 2.f * g_v[1][i] + 2.f * g_v[2][i] + g_v[3][i]);
    if (i < B_) {
        float t0 = 0.f, t1 = 0.f, t2 = 0.f, t3 = 0.f;
#pragma unroll
        for (int p = 0; p < 8; p++) {
            t0 += g_trp[0][p][i];
            t1 += g_trp[1][p][i];
            t2 += g_trp[2][p][i];
            t3 += g_trp[3][p][i];
        }
        g_ljt[i] += c * (t0 + 2.f * t1 + 2.f * t2 + t3);
    }
}

__global__ void final_kernel(float* __restrict__ out)
{
    int row = blockIdx.x * 8 + (threadIdx.x >> 5);
    int lane = threadIdx.x & 31;
    const float* xr = g_xt + (size_t)row * D_;
    float s = 0.f;
#pragma unroll
    for (int c = 0; c < D_; c += 32) { float v = xr[c + lane]; s += v * v; }
#pragma unroll
    for (int o = 16; o > 0; o >>= 1) s += __shfl_xor_sync(0xffffffffu, s, o);
    if (lane == 0) out[row] = -0.5f * s - 235.2482645f - g_ljt[row];
}

// ---------------- launch ----------------
extern "C" void kernel_launch(void* const* d_in, const int* in_sizes, int n_in,
                              void* d_out, int out_size)
{
    const float* x  = (const float*)d_in[0];
    const float* W1 = (const float*)d_in[1];
    const float* b1 = (const float*)d_in[2];
    const float* W2 = (const float*)d_in[3];
    const float* b2 = (const float*)d_in[4];
    const float* W3 = (const float*)d_in[5];
    const float* b3 = (const float*)d_in[6];
    const float* pj = (const float*)d_in[7];
    float* out = (float*)d_out;

    float *noise, *h1, *dh1, *h2, *dh2, *vbase, *trbase, *xt, *xe;
    cudaGetSymbolAddress((void**)&noise,  g_noise);
    cudaGetSymbolAddress((void**)&h1,     g_h1);
    cudaGetSymbolAddress((void**)&dh1,    g_dh1);
    cudaGetSymbolAddress((void**)&h2,     g_h2);
    cudaGetSymbolAddress((void**)&dh2,    g_dh2);
    cudaGetSymbolAddress((void**)&vbase,  g_v);
    cudaGetSymbolAddress((void**)&trbase, g_trp);
    cudaGetSymbolAddress((void**)&xt,     g_xt);
    cudaGetSymbolAddress((void**)&xe,     g_xe);

    dim3 blk(128);
    dim3 gridH(H_ / 64, B_ / 64);
    dim3 gridD(D_ / 64, B_ / 64);

    noise_kernel<<<dim3(D_ / 64, B_ / 64), dim3(16, 16)>>>(x, pj);
    init_kernel<<<(B_ * D_) / 256, 256>>>(x);

    const float dt = -0.1f;
    for (int k = 0; k < 10; k++) {
        float t = 1.0f + dt * (float)k;
        struct Ev { const float* xin; float tt; int slot; float c; };
        Ev evals[4] = {
            { xt, t,              0, dt * 0.5f },
            { xe, t + dt * 0.5f,  1, dt * 0.5f },
            { xe, t + dt * 0.5f,  2, dt        },
            { xe, t + dt,         3, 0.f       },
        };
        for (int d = 0; d < 4; d++) {
            gemm_tanh_kernel<<<gridH, blk>>>(evals[d].xin, noise, W1, b1,
                                             W1 + 256 * H_, evals[d].tt,
                                             h1, dh1, D_, H_);
            gemm_tanh_kernel<<<gridH, blk>>>(h1, dh1, W2, b2, nullptr, 0.f,
                                             h2, dh2, H_, H_);
            gemm_out_kernel<<<gridD, blk>>>(h2, dh2, W3, b3, H_, D_,
                                            vbase + (size_t)evals[d].slot * B_ * D_,
                                            trbase + (size_t)evals[d].slot * 8 * B_,
                                            noise, xt, xe, evals[d].c);
        }
        combine_kernel<<<(B_ * D_) / 256, 256>>>(dt / 6.f);
    }
    final_kernel<<<B_ / 8, 256>>>(out);
}

// round 3
// speedup vs baseline: 2.2088x; 2.2088x over previous
#include <cuda_runtime.h>
#include <cuda_bf16.h>
#include <cstdint>
#include <cstddef>

#define B_ 16384
#define D_ 256
#define H_ 1024

// ---------------- scratch (device globals: no allocation allowed) ----------------
__device__ float g_noise[B_ * D_];
__device__ float g_z1t[B_ * H_];
__device__ __nv_bfloat16 g_h1b[B_ * H_];
__device__ __nv_bfloat16 g_dh1b[B_ * H_];
__device__ __nv_bfloat16 g_h2b[B_ * H_];
__device__ __nv_bfloat16 g_dh2b[B_ * H_];
__device__ __nv_bfloat16 g_W1b[(D_ + 1) * H_];
__device__ __nv_bfloat16 g_W2b[H_ * H_];
__device__ __nv_bfloat16 g_W3b[H_ * D_];
__device__ float g_v[4][B_ * D_];
__device__ float g_trp[4][8][B_];
__device__ float g_xt[B_ * D_];
__device__ float g_xe[B_ * D_];
__device__ float g_ljt[B_];

// ---------------- PTX helpers ----------------
__device__ __forceinline__ uint32_t smem_u32(const void* p) {
    uint32_t a;
    asm("{ .reg .u64 t; cvta.to.shared.u64 t, %1; cvt.u32.u64 %0, t; }" : "=r"(a) : "l"(p));
    return a;
}

#define CP_ASYNC16(dst, src) \
    asm volatile("cp.async.cg.shared.global [%0], [%1], 16;" :: "r"(dst), "l"(src) : "memory")
#define CP_COMMIT() asm volatile("cp.async.commit_group;" ::: "memory")
#define CP_WAIT(n)  asm volatile("cp.async.wait_group %0;" :: "n"(n) : "memory")

#define LDSM4(r0, r1, r2, r3, a) \
    asm volatile("ldmatrix.sync.aligned.m8n8.x4.shared.b16 {%0,%1,%2,%3}, [%4];" \
        : "=r"(r0), "=r"(r1), "=r"(r2), "=r"(r3) : "r"(a))
#define LDSM2T(r0, r1, a) \
    asm volatile("ldmatrix.sync.aligned.m8n8.x2.trans.shared.b16 {%0,%1}, [%2];" \
        : "=r"(r0), "=r"(r1) : "r"(a))

#define MMA16816(d, a, b) \
    asm volatile("mma.sync.aligned.m16n8k16.row.col.f32.bf16.bf16.f32 " \
        "{%0,%1,%2,%3}, {%4,%5,%6,%7}, {%8,%9}, {%0,%1,%2,%3};" \
        : "+f"((d)[0]), "+f"((d)[1]), "+f"((d)[2]), "+f"((d)[3]) \
        : "r"((a)[0]), "r"((a)[1]), "r"((a)[2]), "r"((a)[3]), "r"((b)[0]), "r"((b)[1]))

// ---------------- tiling ----------------
// CTA: 256 threads (8 warps, 4(M) x 2(N)); tile M=128, N=64, K-chunk 32.
// Warp tile: 32(M) x 32(N), dual-stream where STREAMS==2.
// A smem rows: 32 bf16 = 64B, padded to 80B (16B-bank permutation 5r%8).
// B smem rows: 64 bf16 = 128B, padded to 144B (permutation 9r%8).
#define OFF_AV(b) (512 + (b) * 10240)
#define OFF_AT(b) (20992 + (b) * 10240)
#define OFF_BB(b) (41472 + (b) * 4608)
#define SMEM_SZ   50688

template <bool AFP32>
__device__ __forceinline__ void stage_A(uint32_t sb, int off, const void* Ap,
                                        int K, int m0, int kc, int tid)
{
    if (AFP32) {
        const float* A = (const float*)Ap;
#pragma unroll
        for (int i = 0; i < 2; i++) {
            int id = tid + i * 256;
            int r = id >> 2, q = id & 3;
            const float* s = A + (size_t)(m0 + r) * K + kc + q * 8;
            float4 u = *(const float4*)s;
            float4 v = *(const float4*)(s + 4);
            __nv_bfloat162 p0 = __floats2bfloat162_rn(u.x, u.y);
            __nv_bfloat162 p1 = __floats2bfloat162_rn(u.z, u.w);
            __nv_bfloat162 p2 = __floats2bfloat162_rn(v.x, v.y);
            __nv_bfloat162 p3 = __floats2bfloat162_rn(v.z, v.w);
            uint32_t d = sb + off + r * 80 + q * 16;
            asm volatile("st.shared.v4.b32 [%0], {%1,%2,%3,%4};" :: "r"(d),
                "r"(*(uint32_t*)&p0), "r"(*(uint32_t*)&p1),
                "r"(*(uint32_t*)&p2), "r"(*(uint32_t*)&p3) : "memory");
        }
    } else {
        const __nv_bfloat16* A = (const __nv_bfloat16*)Ap;
#pragma unroll
        for (int i = 0; i < 2; i++) {
            int id = tid + i * 256;
            int r = id >> 2, q = id & 3;
            const __nv_bfloat16* s = A + (size_t)(m0 + r) * K + kc + q * 8;
            CP_ASYNC16(sb + off + r * 80 + q * 16, s);
        }
    }
}

__device__ __forceinline__ void stage_B(uint32_t sb, int off, const __nv_bfloat16* W,
                                        int Ntot, int n0, int kc, int tid)
{
    int r = tid >> 3, cn = tid & 7;   // 32 rows x 8 x 16B chunks
    const __nv_bfloat16* s = W + (size_t)(kc + r) * Ntot + n0 + cn * 8;
    CP_ASYNC16(sb + off + r * 144 + cn * 16, s);
}

// MODE 0: hidden layer  -> Ho=tanh(zv+beff) bf16, Do=(1-h^2)*zt bf16 (zt from acct or Z1T)
// MODE 1: output layer  -> Vo=zv+bias fp32, Xe=Xt+cEval*Vo, trace partials from Noise*zt
// MODE 2: raw GEMM      -> Ho = zv fp32 (z1t precompute)
template <int STREAMS, int MODE, bool AFP32>
__global__ void __launch_bounds__(256)
gemm_bf16(const void* __restrict__ Avp, const void* __restrict__ Atp,
          const __nv_bfloat16* __restrict__ Wb,
          const float* __restrict__ bias, const float* __restrict__ wt, float tval,
          int K, int Ntot,
          void* __restrict__ Hop, void* __restrict__ Dop,
          const float* __restrict__ Z1T,
          float* __restrict__ Trp, const float* __restrict__ Noise,
          const float* __restrict__ Xt, float* __restrict__ Xe, float cEval)
{
    extern __shared__ char smem[];
    float* beff = (float*)smem;
    const uint32_t sb = smem_u32(smem);
    const int tid = threadIdx.x;
    const int lane = tid & 31, warp = tid >> 5;
    const int m0 = blockIdx.y * 128, n0 = blockIdx.x * 64;
    const int wm = warp >> 1, wn = warp & 1;

    if (MODE != 2 && tid < 64) {
        float be = bias[n0 + tid];
        if (MODE == 0 && wt) be += tval * wt[n0 + tid];
        beff[tid] = be;
    }

    float accv[2][4][4];
    float acct[2][4][4];
#pragma unroll
    for (int mi = 0; mi < 2; mi++)
#pragma unroll
        for (int ni = 0; ni < 4; ni++)
#pragma unroll
            for (int e = 0; e < 4; e++) { accv[mi][ni][e] = 0.f; acct[mi][ni][e] = 0.f; }

    const int NC = K / 32;

    // prologue stage chunk 0
    {
        stage_A<AFP32>(sb, OFF_AV(0), Avp, K, m0, 0, tid);
        if (STREAMS == 2) stage_A<AFP32>(sb, OFF_AT(0), Atp, K, m0, 0, tid);
        stage_B(sb, OFF_BB(0), Wb, Ntot, n0, 0, tid);
        CP_COMMIT();
    }

    const int lrow = ((lane >> 3) & 1) * 8 + (lane & 7);   // ldmatrix x4 lane->row
    const int lk8  = (lane >> 4) * 8;                      // ldmatrix x4 lane->k-half
    const int bk   = lane & 15;                            // ldmatrix x2 lane->k row

    for (int c = 0; c < NC; c++) {
        const int b = c & 1;
        if (c + 1 < NC) {
            const int nb = (c + 1) & 1;
            stage_A<AFP32>(sb, OFF_AV(nb), Avp, K, m0, (c + 1) * 32, tid);
            if (STREAMS == 2) stage_A<AFP32>(sb, OFF_AT(nb), Atp, K, m0, (c + 1) * 32, tid);
            stage_B(sb, OFF_BB(nb), Wb, Ntot, n0, (c + 1) * 32, tid);
            CP_COMMIT();
            CP_WAIT(1);
        } else {
            CP_WAIT(0);
        }
        __syncthreads();

        const uint32_t aav = sb + OFF_AV(b) + (wm * 32 + lrow) * 80 + lk8 * 2;
        const uint32_t aat = sb + OFF_AT(b) + (wm * 32 + lrow) * 80 + lk8 * 2;
        const uint32_t ab  = sb + OFF_BB(b) + bk * 144 + wn * 64;
#pragma unroll
        for (int kk = 0; kk < 2; kk++) {
            uint32_t av[2][4], at[2][4], bf[4][2];
#pragma unroll
            for (int mi = 0; mi < 2; mi++)
                LDSM4(av[mi][0], av[mi][1], av[mi][2], av[mi][3],
                      aav + mi * 1280 + kk * 32);
            if (STREAMS == 2) {
#pragma unroll
                for (int mi = 0; mi < 2; mi++)
                    LDSM4(at[mi][0], at[mi][1], at[mi][2], at[mi][3],
                          aat + mi * 1280 + kk * 32);
            }
#pragma unroll
            for (int ni = 0; ni < 4; ni++)
                LDSM2T(bf[ni][0], bf[ni][1], ab + kk * 2304 + ni * 16);
#pragma unroll
            for (int mi = 0; mi < 2; mi++)
#pragma unroll
                for (int ni = 0; ni < 4; ni++) {
                    MMA16816(accv[mi][ni], av[mi], bf[ni]);
                    if (STREAMS == 2) MMA16816(acct[mi][ni], at[mi], bf[ni]);
                }
        }
        __syncthreads();
    }

    // ---------------- epilogue ----------------
    const int g = lane >> 2, tg = lane & 3;
    float trs[2][2] = {{0.f, 0.f}, {0.f, 0.f}};
#pragma unroll
    for (int mi = 0; mi < 2; mi++)
#pragma unroll
        for (int ni = 0; ni < 4; ni++) {
            const int colp = wn * 32 + ni * 8 + 2 * tg;
            const int colg = n0 + colp;
#pragma unroll
            for (int rh = 0; rh < 2; rh++) {
                const int row = m0 + wm * 32 + mi * 16 + rh * 8 + g;
                const float z0 = accv[mi][ni][rh * 2 + 0];
                const float z1 = accv[mi][ni][rh * 2 + 1];
                if (MODE == 2) {
                    float2 o; o.x = z0; o.y = z1;
                    *(float2*)((float*)Hop + (size_t)row * Ntot + colg) = o;
                } else if (MODE == 0) {
                    const float h0 = tanhf(z0 + beff[colp]);
                    const float h1 = tanhf(z1 + beff[colp + 1]);
                    float d0, d1;
                    if (STREAMS == 2) {
                        d0 = (1.f - h0 * h0) * acct[mi][ni][rh * 2 + 0];
                        d1 = (1.f - h1 * h1) * acct[mi][ni][rh * 2 + 1];
                    } else {
                        float2 zt = *(const float2*)(Z1T + (size_t)row * Ntot + colg);
                        d0 = (1.f - h0 * h0) * zt.x;
                        d1 = (1.f - h1 * h1) * zt.y;
                    }
                    *(__nv_bfloat162*)((__nv_bfloat16*)Hop + (size_t)row * Ntot + colg) =
                        __floats2bfloat162_rn(h0, h1);
                    *(__nv_bfloat162*)((__nv_bfloat16*)Dop + (size_t)row * Ntot + colg) =
                        __floats2bfloat162_rn(d0, d1);
                } else {
                    const float v0 = z0 + beff[colp];
                    const float v1 = z1 + beff[colp + 1];
                    const size_t o = (size_t)row * 256 + colg;
                    float2 vv; vv.x = v0; vv.y = v1;
                    *(float2*)((float*)Hop + o) = vv;
                    if (cEval != 0.f) {
                        float2 x2 = *(const float2*)(Xt + o);
                        float2 e2; e2.x = x2.x + cEval * v0; e2.y = x2.y + cEval * v1;
                        *(float2*)(Xe + o) = e2;
                    }
                    float2 nz = *(const float2*)(Noise + o);
                    trs[mi][rh] += nz.x * acct[mi][ni][rh * 2 + 0]
                                 + nz.y * acct[mi][ni][rh * 2 + 1];
                }
            }
        }
    if (MODE == 1) {
#pragma unroll
        for (int mi = 0; mi < 2; mi++)
#pragma unroll
            for (int rh = 0; rh < 2; rh++) {
                float s = trs[mi][rh];
                s += __shfl_xor_sync(0xffffffffu, s, 1);
                s += __shfl_xor_sync(0xffffffffu, s, 2);
                if (tg == 0) {
                    const int row = m0 + wm * 32 + mi * 16 + rh * 8 + g;
                    Trp[(size_t)(blockIdx.x * 2 + wn) * B_ + row] = s;
                }
            }
    }
}

// ---------------- fp32 -> bf16 weight conversion ----------------
__global__ void __launch_bounds__(256)
cvt_bf16_kernel(const float* __restrict__ in, __nv_bfloat16* __restrict__ out, int n)
{
    int i = blockIdx.x * 256 + threadIdx.x;
    if (i < n) out[i] = __float2bfloat16(in[i]);
}

// ---------------- noise = sin(1000*(x@proj))*sqrt(2), plain fp32 ----------------
__global__ void __launch_bounds__(256)
noise_kernel(const float* __restrict__ X, const float* __restrict__ P)
{
    __shared__ float As[64][17];
    __shared__ float Bs[16][68];
    int bm = blockIdx.y * 64, bn = blockIdx.x * 64;
    int tx = threadIdx.x, ty = threadIdx.y;
    int tid = ty * 16 + tx;
    float acc[4][4];
#pragma unroll
    for (int i = 0; i < 4; i++)
#pragma unroll
        for (int j = 0; j < 4; j++) acc[i][j] = 0.f;

    for (int k0 = 0; k0 < D_; k0 += 16) {
        int ar = tid >> 2, ac = (tid & 3) * 4;
        float4 a4 = *(const float4*)(X + (size_t)(bm + ar) * D_ + k0 + ac);
        As[ar][ac + 0] = a4.x; As[ar][ac + 1] = a4.y; As[ar][ac + 2] = a4.z; As[ar][ac + 3] = a4.w;
        int br = tid >> 4, bc = (tid & 15) * 4;
        float4 b4 = *(const float4*)(P + (size_t)(k0 + br) * D_ + bn + bc);
        Bs[br][bc + 0] = b4.x; Bs[br][bc + 1] = b4.y; Bs[br][bc + 2] = b4.z; Bs[br][bc + 3] = b4.w;
        __syncthreads();
#pragma unroll
        for (int k = 0; k < 16; k++) {
            float a[4], b[4];
#pragma unroll
            for (int i = 0; i < 4; i++) a[i] = As[ty * 4 + i][k];
#pragma unroll
            for (int j = 0; j < 4; j++) b[j] = Bs[k][tx * 4 + j];
#pragma unroll
            for (int i = 0; i < 4; i++)
#pragma unroll
                for (int j = 0; j < 4; j++) acc[i][j] = fmaf(a[i], b[j], acc[i][j]);
        }
        __syncthreads();
    }
#pragma unroll
    for (int i = 0; i < 4; i++)
#pragma unroll
        for (int j = 0; j < 4; j++)
            g_noise[(size_t)(bm + ty * 4 + i) * D_ + bn + tx * 4 + j] =
                sinf(1000.f * acc[i][j]) * 1.41421356f;
}

// ---------------- small kernels ----------------
__global__ void init_kernel(const float* __restrict__ X)
{
    int i = blockIdx.x * blockDim.x + threadIdx.x;
    g_xt[i] = X[i];
    if (i < B_) g_ljt[i] = 0.f;
}

__global__ void combine_kernel(float c)   // c = dt/6
{
    int i = blockIdx.x * blockDim.x + threadIdx.x;
    g_xt[i] += c * (g_v[0][i] + 2.f * g_v[1][i] + 2.f * g_v[2][i] + g_v[3][i]);
    if (i < B_) {
        float t0 = 0.f, t1 = 0.f, t2 = 0.f, t3 = 0.f;
#pragma unroll
        for (int p = 0; p < 8; p++) {
            t0 += g_trp[0][p][i];
            t1 += g_trp[1][p][i];
            t2 += g_trp[2][p][i];
            t3 += g_trp[3][p][i];
        }
        g_ljt[i] += c * (t0 + 2.f * t1 + 2.f * t2 + t3);
    }
}

__global__ void final_kernel(float* __restrict__ out)
{
    int row = blockIdx.x * 8 + (threadIdx.x >> 5);
    int lane = threadIdx.x & 31;
    const float* xr = g_xt + (size_t)row * D_;
    float s = 0.f;
#pragma unroll
    for (int c = 0; c < D_; c += 32) { float v = xr[c + lane]; s += v * v; }
#pragma unroll
    for (int o = 16; o > 0; o >>= 1) s += __shfl_xor_sync(0xffffffffu, s, o);
    if (lane == 0) out[row] = -0.5f * s - 235.2482645f - g_ljt[row];
}

// ---------------- launch ----------------
extern "C" void kernel_launch(void* const* d_in, const int* in_sizes, int n_in,
                              void* d_out, int out_size)
{
    const float* x  = (const float*)d_in[0];
    const float* W1 = (const float*)d_in[1];
    const float* b1 = (const float*)d_in[2];
    const float* W2 = (const float*)d_in[3];
    const float* b2 = (const float*)d_in[4];
    const float* W3 = (const float*)d_in[5];
    const float* b3 = (const float*)d_in[6];
    const float* pj = (const float*)d_in[7];
    float* out = (float*)d_out;

    float *noise, *z1t, *vbase, *trbase, *xt, *xe;
    __nv_bfloat16 *h1b, *dh1b, *h2b, *dh2b, *w1b, *w2b, *w3b;
    cudaGetSymbolAddress((void**)&noise,  g_noise);
    cudaGetSymbolAddress((void**)&z1t,    g_z1t);
    cudaGetSymbolAddress((void**)&h1b,    g_h1b);
    cudaGetSymbolAddress((void**)&dh1b,   g_dh1b);
    cudaGetSymbolAddress((void**)&h2b,    g_h2b);
    cudaGetSymbolAddress((void**)&dh2b,   g_dh2b);
    cudaGetSymbolAddress((void**)&w1b,    g_W1b);
    cudaGetSymbolAddress((void**)&w2b,    g_W2b);
    cudaGetSymbolAddress((void**)&w3b,    g_W3b);
    cudaGetSymbolAddress((void**)&vbase,  g_v);
    cudaGetSymbolAddress((void**)&trbase, g_trp);
    cudaGetSymbolAddress((void**)&xt,     g_xt);
    cudaGetSymbolAddress((void**)&xe,     g_xe);

    cudaFuncSetAttribute(gemm_bf16<1, 0, true>,  cudaFuncAttributeMaxDynamicSharedMemorySize, SMEM_SZ);
    cudaFuncSetAttribute(gemm_bf16<2, 0, false>, cudaFuncAttributeMaxDynamicSharedMemorySize, SMEM_SZ);
    cudaFuncSetAttribute(gemm_bf16<2, 1, false>, cudaFuncAttributeMaxDynamicSharedMemorySize, SMEM_SZ);
    cudaFuncSetAttribute(gemm_bf16<1, 2, true>,  cudaFuncAttributeMaxDynamicSharedMemorySize, SMEM_SZ);

    // prep
    cvt_bf16_kernel<<<((D_ + 1) * H_ + 255) / 256, 256>>>(W1, w1b, (D_ + 1) * H_);
    cvt_bf16_kernel<<<(H_ * H_ + 255) / 256, 256>>>(W2, w2b, H_ * H_);
    cvt_bf16_kernel<<<(H_ * D_ + 255) / 256, 256>>>(W3, w3b, H_ * D_);
    noise_kernel<<<dim3(D_ / 64, B_ / 64), dim3(16, 16)>>>(x, pj);
    init_kernel<<<(B_ * D_) / 256, 256>>>(x);

    dim3 gridH(H_ / 64, B_ / 128);    // 16 x 128
    dim3 gridD(D_ / 64, B_ / 128);    // 4 x 128

    // z1t = noise @ W1[0:256]  (constant across all evaluations)
    gemm_bf16<1, 2, true><<<gridH, 256, SMEM_SZ>>>(
        noise, nullptr, w1b, nullptr, nullptr, 0.f, D_, H_,
        z1t, nullptr, nullptr, nullptr, nullptr, nullptr, nullptr, 0.f);

    const float dt = -0.1f;
    for (int k = 0; k < 10; k++) {
        float t = 1.0f + dt * (float)k;
        struct Ev { const float* xin; float tt; int slot; float c; };
        Ev evals[4] = {
            { xt, t,              0, dt * 0.5f },
            { xe, t + dt * 0.5f,  1, dt * 0.5f },
            { xe, t + dt * 0.5f,  2, dt        },
            { xe, t + dt,         3, 0.f       },
        };
        for (int d = 0; d < 4; d++) {
            gemm_bf16<1, 0, true><<<gridH, 256, SMEM_SZ>>>(
                evals[d].xin, nullptr, w1b, b1, W1 + 256 * H_, evals[d].tt, D_, H_,
                h1b, dh1b, z1t, nullptr, nullptr, nullptr, nullptr, 0.f);
            gemm_bf16<2, 0, false><<<gridH, 256, SMEM_SZ>>>(
                h1b, dh1b, w2b, b2, nullptr, 0.f, H_, H_,
                h2b, dh2b, nullptr, nullptr, nullptr, nullptr, nullptr, 0.f);
            gemm_bf16<2, 1, false><<<gridD, 256, SMEM_SZ>>>(
                h2b, dh2b, w3b, b3, nullptr, 0.f, H_, D_,
                vbase + (size_t)evals[d].slot * B_ * D_, nullptr, nullptr,
                trbase + (size_t)evals[d].slot * 8 * B_,
                noise, xt, xe, evals[d].c);
        }
        combine_kernel<<<(B_ * D_) / 256, 256>>>(dt / 6.f);
    }
    final_kernel<<<B_ / 8, 256>>>(out);
}